// round 1
// baseline (speedup 1.0000x reference)
#include <cuda_runtime.h>

#define NN 200000
#define NE 6400000

// ---- scratch (device globals; no allocations allowed) ----
__device__ float g_deg[NN];
__device__ float g_dinv[NN];
__device__ float g_h1[NN * 16];    // h1 * dinv[i]  (pre-scaled for scatter)
__device__ float g_agg1[NN * 16];  // init = self-loop contribution (h1*dinv); final *= dinv
__device__ float g_h2[NN * 6];     // h2 * dinv[i]
__device__ float g_agg2[NN * 6];
__device__ int   g_is64;

// ---- dtype detection: int64 little-endian high words of values <2^31 are 0 ----
__global__ void k_detect(const unsigned int* w) {
    if (blockIdx.x == 0 && threadIdx.x == 0) {
        int is64 = 1;
        #pragma unroll
        for (int i = 1; i < 32; i += 2)
            if (w[i] != 0u) is64 = 0;
        g_is64 = is64;
    }
}

__device__ __forceinline__ int edge_at(const void* ei, long long idx) {
    if (g_is64) return (int)((const long long*)ei)[idx];
    return ((const int*)ei)[idx];
}

__global__ void k_initdeg() {
    int i = blockIdx.x * blockDim.x + threadIdx.x;
    if (i < NN) g_deg[i] = 1.0f;  // self-loop
}

__global__ void k_degree(const void* ei) {
    int e = blockIdx.x * blockDim.x + threadIdx.x;
    if (e >= NE) return;
    int d = edge_at(ei, (long long)NE + e);
    atomicAdd(&g_deg[d], 1.0f);
}

// dinv + layer-1 GEMM (x[21] @ W1[21x16]), pre-scaled by dinv, self-loop init
__global__ void k_layer1_node(const float* __restrict__ x, const float* __restrict__ W1) {
    __shared__ float sW[21 * 16];
    for (int t = threadIdx.x; t < 21 * 16; t += blockDim.x) sW[t] = W1[t];
    __syncthreads();
    int i = blockIdx.x * blockDim.x + threadIdx.x;
    if (i >= NN) return;
    float di = rsqrtf(g_deg[i]);
    g_dinv[i] = di;
    float xi[21];
    #pragma unroll
    for (int k = 0; k < 21; k++) xi[k] = x[i * 21 + k];
    #pragma unroll
    for (int f = 0; f < 16; f++) {
        float s = 0.0f;
        #pragma unroll
        for (int k = 0; k < 21; k++) s = fmaf(xi[k], sW[k * 16 + f], s);
        s *= di;                        // one dinv factor now, second applied per-dst later
        g_h1[i * 16 + f]   = s;
        g_agg1[i * 16 + f] = s;         // self-loop: h1*dinv (becomes h1*dinv^2 after final scale)
    }
}

// scatter layer 1: thread = (edge, feat), 16 feats/edge
__global__ void k_scatter1(const void* __restrict__ ei) {
    long long t = (long long)blockIdx.x * blockDim.x + threadIdx.x;
    if (t >= (long long)NE * 16) return;
    int e = (int)(t >> 4);
    int f = (int)(t & 15);
    int s = edge_at(ei, e);
    int d = edge_at(ei, (long long)NE + e);
    atomicAdd(&g_agg1[d * 16 + f], g_h1[s * 16 + f]);
}

// relu(agg1*dinv + b1) @ W2[16x6], pre-scale, self-loop init
__global__ void k_layer2_node(const float* __restrict__ b1, const float* __restrict__ W2) {
    __shared__ float sW[16 * 6];
    __shared__ float sb[16];
    for (int t = threadIdx.x; t < 96; t += blockDim.x) sW[t] = W2[t];
    if (threadIdx.x < 16) sb[threadIdx.x] = b1[threadIdx.x];
    __syncthreads();
    int i = blockIdx.x * blockDim.x + threadIdx.x;
    if (i >= NN) return;
    float di = g_dinv[i];
    float v[16];
    #pragma unroll
    for (int f = 0; f < 16; f++)
        v[f] = fmaxf(g_agg1[i * 16 + f] * di + sb[f], 0.0f);
    #pragma unroll
    for (int j = 0; j < 6; j++) {
        float s = 0.0f;
        #pragma unroll
        for (int f = 0; f < 16; f++) s = fmaf(v[f], sW[f * 6 + j], s);
        s *= di;
        g_h2[i * 6 + j]   = s;
        g_agg2[i * 6 + j] = s;
    }
}

// scatter layer 2: thread = (edge, feat), 6 feats/edge
__global__ void k_scatter2(const void* __restrict__ ei) {
    long long t = (long long)blockIdx.x * blockDim.x + threadIdx.x;
    if (t >= (long long)NE * 6) return;
    int e = (int)(t / 6);
    int f = (int)(t - (long long)e * 6);
    int s = edge_at(ei, e);
    int d = edge_at(ei, (long long)NE + e);
    atomicAdd(&g_agg2[d * 6 + f], g_h2[s * 6 + f]);
}

// final: agg2*dinv + b2, log_softmax over 6 classes
__global__ void k_out(const float* __restrict__ b2, float* __restrict__ out) {
    int i = blockIdx.x * blockDim.x + threadIdx.x;
    if (i >= NN) return;
    float di = g_dinv[i];
    float v[6];
    float m = -1e30f;
    #pragma unroll
    for (int j = 0; j < 6; j++) {
        v[j] = g_agg2[i * 6 + j] * di + b2[j];
        m = fmaxf(m, v[j]);
    }
    float s = 0.0f;
    #pragma unroll
    for (int j = 0; j < 6; j++) s += expf(v[j] - m);
    float l = m + logf(s);
    #pragma unroll
    for (int j = 0; j < 6; j++) out[i * 6 + j] = v[j] - l;
}

extern "C" void kernel_launch(void* const* d_in, const int* in_sizes, int n_in,
                              void* d_out, int out_size) {
    const float* x  = (const float*)d_in[0];
    const void*  ei = d_in[1];
    const float* W1 = (const float*)d_in[2];
    const float* b1 = (const float*)d_in[3];
    const float* W2 = (const float*)d_in[4];
    const float* b2 = (const float*)d_in[5];
    float* out = (float*)d_out;

    const int T = 256;
    k_detect<<<1, 32>>>((const unsigned int*)ei);
    k_initdeg<<<(NN + T - 1) / T, T>>>();
    k_degree<<<(NE + T - 1) / T, T>>>(ei);
    k_layer1_node<<<(NN + T - 1) / T, T>>>(x, W1);
    {
        long long n = (long long)NE * 16;
        k_scatter1<<<(unsigned int)((n + T - 1) / T), T>>>(ei);
    }
    k_layer2_node<<<(NN + T - 1) / T, T>>>(b1, W2);
    {
        long long n = (long long)NE * 6;
        k_scatter2<<<(unsigned int)((n + T - 1) / T), T>>>(ei);
    }
    k_out<<<(NN + T - 1) / T, T>>>(b2, out);
}

// round 2
// speedup vs baseline: 1.4587x; 1.4587x over previous
#include <cuda_runtime.h>

#define NN 200000
#define NE 6400000

// ---- scratch (device globals; no allocations allowed) ----
__device__ float g_deg[NN];
__device__ float g_dinv[NN];
__device__ int   g_src32[NE];
__device__ int   g_dst32[NE];
__device__ float g_h1[NN * 16];   // h1 * dinv[i]
__device__ float g_agg1[NN * 16]; // init = self-loop term
__device__ float g_h2[NN * 8];    // h2 * dinv[i], padded to 8 for float4
__device__ float g_agg2[NN * 8];  // padded to 8 for red.v4 alignment
__device__ int   g_is64;

// ---- dtype detection: int64 little-endian high words of values <2^31 are 0 ----
__global__ void k_detect(const unsigned int* w) {
    if (blockIdx.x == 0 && threadIdx.x == 0) {
        int is64 = 1;
        #pragma unroll
        for (int i = 1; i < 32; i += 2)
            if (w[i] != 0u) is64 = 0;
        g_is64 = is64;
    }
}

__global__ void k_initdeg() {
    int i = blockIdx.x * blockDim.x + threadIdx.x;
    if (i < NN) g_deg[i] = 1.0f;  // self-loop
}

// fused: int64/int32 edge conversion + degree histogram
__global__ void k_convert_degree(const void* __restrict__ ei) {
    int e = blockIdx.x * blockDim.x + threadIdx.x;
    if (e >= NE) return;
    int s, d;
    if (g_is64) {
        const long long* p = (const long long*)ei;
        s = (int)p[e];
        d = (int)p[(long long)NE + e];
    } else {
        const int* p = (const int*)ei;
        s = p[e];
        d = p[NE + e];
    }
    g_src32[e] = s;
    g_dst32[e] = d;
    atomicAdd(&g_deg[d], 1.0f);
}

// dinv + layer-1 GEMM (x[21] @ W1[21x16]), x tiled through smem, pre-scaled by dinv
__global__ void k_layer1_node(const float* __restrict__ x, const float* __restrict__ W1) {
    __shared__ float sW[21 * 16];
    __shared__ float sX[256 * 21];
    for (int t = threadIdx.x; t < 21 * 16; t += blockDim.x) sW[t] = W1[t];
    int base = blockIdx.x * 256;
    {
        long long gbase = (long long)base * 21;
        int lim = (NN - base) * 21;
        if (lim > 256 * 21) lim = 256 * 21;
        for (int t = threadIdx.x; t < lim; t += blockDim.x)
            sX[t] = x[gbase + t];
    }
    __syncthreads();
    int i = base + threadIdx.x;
    if (i >= NN) return;
    float di = rsqrtf(g_deg[i]);
    g_dinv[i] = di;
    const float* xi = &sX[threadIdx.x * 21];
    float acc[16];
    #pragma unroll
    for (int f = 0; f < 16; f++) acc[f] = 0.0f;
    #pragma unroll
    for (int k = 0; k < 21; k++) {
        float xk = xi[k];
        #pragma unroll
        for (int f = 0; f < 16; f++) acc[f] = fmaf(xk, sW[k * 16 + f], acc[f]);
    }
    float4* h1p = (float4*)&g_h1[i * 16];
    float4* a1p = (float4*)&g_agg1[i * 16];
    #pragma unroll
    for (int q = 0; q < 4; q++) {
        float4 v;
        v.x = acc[q * 4 + 0] * di;
        v.y = acc[q * 4 + 1] * di;
        v.z = acc[q * 4 + 2] * di;
        v.w = acc[q * 4 + 3] * di;
        h1p[q] = v;
        a1p[q] = v;  // self-loop contribution
    }
}

__device__ __forceinline__ void red_v4(float* p, float4 v) {
    asm volatile("red.global.add.v4.f32 [%0], {%1,%2,%3,%4};"
                 :: "l"(p), "f"(v.x), "f"(v.y), "f"(v.z), "f"(v.w) : "memory");
}
__device__ __forceinline__ void red_v2(float* p, float2 v) {
    asm volatile("red.global.add.v2.f32 [%0], {%1,%2};"
                 :: "l"(p), "f"(v.x), "f"(v.y) : "memory");
}

// scatter layer 1: one thread per edge, 4x red.v4
__global__ void k_scatter1() {
    int e = blockIdx.x * blockDim.x + threadIdx.x;
    if (e >= NE) return;
    int s = g_src32[e];
    int d = g_dst32[e];
    const float4* hp = (const float4*)&g_h1[s * 16];
    float* ap = &g_agg1[d * 16];
    #pragma unroll
    for (int q = 0; q < 4; q++)
        red_v4(ap + q * 4, hp[q]);
}

// relu(agg1*dinv + b1) @ W2[16x6], pre-scale, self-loop init (rows padded to 8)
__global__ void k_layer2_node(const float* __restrict__ b1, const float* __restrict__ W2) {
    __shared__ float sW[16 * 6];
    __shared__ float sb[16];
    for (int t = threadIdx.x; t < 96; t += blockDim.x) sW[t] = W2[t];
    if (threadIdx.x < 16) sb[threadIdx.x] = b1[threadIdx.x];
    __syncthreads();
    int i = blockIdx.x * blockDim.x + threadIdx.x;
    if (i >= NN) return;
    float di = g_dinv[i];
    float v[16];
    const float4* a1p = (const float4*)&g_agg1[i * 16];
    #pragma unroll
    for (int q = 0; q < 4; q++) {
        float4 a = a1p[q];
        v[q * 4 + 0] = fmaxf(a.x * di + sb[q * 4 + 0], 0.0f);
        v[q * 4 + 1] = fmaxf(a.y * di + sb[q * 4 + 1], 0.0f);
        v[q * 4 + 2] = fmaxf(a.z * di + sb[q * 4 + 2], 0.0f);
        v[q * 4 + 3] = fmaxf(a.w * di + sb[q * 4 + 3], 0.0f);
    }
    float o[6];
    #pragma unroll
    for (int j = 0; j < 6; j++) {
        float s = 0.0f;
        #pragma unroll
        for (int f = 0; f < 16; f++) s = fmaf(v[f], sW[f * 6 + j], s);
        o[j] = s * di;
    }
    float4 lo = make_float4(o[0], o[1], o[2], o[3]);
    float4 hi = make_float4(o[4], o[5], 0.0f, 0.0f);
    *(float4*)&g_h2[i * 8]       = lo;
    *(float4*)&g_h2[i * 8 + 4]   = hi;
    *(float4*)&g_agg2[i * 8]     = lo;  // self-loop
    *(float4*)&g_agg2[i * 8 + 4] = hi;
}

// scatter layer 2: one thread per edge, red.v4 + red.v2
__global__ void k_scatter2() {
    int e = blockIdx.x * blockDim.x + threadIdx.x;
    if (e >= NE) return;
    int s = g_src32[e];
    int d = g_dst32[e];
    float4 lo = *(const float4*)&g_h2[s * 8];
    float2 hi = *(const float2*)&g_h2[s * 8 + 4];
    float* ap = &g_agg2[d * 8];
    red_v4(ap, lo);
    red_v2(ap + 4, hi);
}

// final: agg2*dinv + b2, log_softmax over 6 classes
__global__ void k_out(const float* __restrict__ b2, float* __restrict__ out) {
    int i = blockIdx.x * blockDim.x + threadIdx.x;
    if (i >= NN) return;
    float di = g_dinv[i];
    float4 lo = *(const float4*)&g_agg2[i * 8];
    float2 hi = *(const float2*)&g_agg2[i * 8 + 4];
    float v[6];
    v[0] = lo.x * di + b2[0];
    v[1] = lo.y * di + b2[1];
    v[2] = lo.z * di + b2[2];
    v[3] = lo.w * di + b2[3];
    v[4] = hi.x * di + b2[4];
    v[5] = hi.y * di + b2[5];
    float m = v[0];
    #pragma unroll
    for (int j = 1; j < 6; j++) m = fmaxf(m, v[j]);
    float s = 0.0f;
    #pragma unroll
    for (int j = 0; j < 6; j++) s += expf(v[j] - m);
    float l = m + logf(s);
    #pragma unroll
    for (int j = 0; j < 6; j++) out[i * 6 + j] = v[j] - l;
}

extern "C" void kernel_launch(void* const* d_in, const int* in_sizes, int n_in,
                              void* d_out, int out_size) {
    const float* x  = (const float*)d_in[0];
    const void*  ei = d_in[1];
    const float* b1 = (const float*)d_in[3];
    const float* W1 = (const float*)d_in[2];
    const float* W2 = (const float*)d_in[4];
    const float* b2 = (const float*)d_in[5];
    float* out = (float*)d_out;

    const int T = 256;
    k_detect<<<1, 32>>>((const unsigned int*)ei);
    k_initdeg<<<(NN + T - 1) / T, T>>>();
    k_convert_degree<<<(NE + T - 1) / T, T>>>(ei);
    k_layer1_node<<<(NN + 255) / 256, 256>>>(x, W1);
    k_scatter1<<<(NE + T - 1) / T, T>>>();
    k_layer2_node<<<(NN + T - 1) / T, T>>>(b1, W2);
    k_scatter2<<<(NE + T - 1) / T, T>>>();
    k_out<<<(NN + T - 1) / T, T>>>(b2, out);
}

// round 3
// speedup vs baseline: 1.8119x; 1.2421x over previous
#include <cuda_runtime.h>

#define NN 200000
#define NE 6400000
#define SCAN_B 512
#define NBLK ((NN + SCAN_B - 1) / SCAN_B)   // 391

// ---- scratch (device globals; no allocations allowed) ----
__device__ int   g_cnt[NN];        // in-degree (excl self-loop)
__device__ int   g_rowstart[NN];
__device__ int   g_cursor[NN];
__device__ int   g_bsum[NBLK];
__device__ int   g_boff[NBLK];
__device__ int   g_src32[NE];
__device__ int   g_dst32[NE];
__device__ int   g_csr[NE];        // src ids grouped by dst
__device__ float g_dinv[NN];
__device__ float g_h1[NN * 16];    // h1 * dinv[i]
__device__ float g_agg1[NN * 16];
__device__ float g_h2[NN * 8];     // h2 * dinv[i], padded to 8
__device__ float g_agg2[NN * 8];
__device__ int   g_is64;

// ---- dtype detection: int64 little-endian high words of values <2^31 are 0 ----
__global__ void k_detect(const unsigned int* w) {
    if (blockIdx.x == 0 && threadIdx.x == 0) {
        int is64 = 1;
        #pragma unroll
        for (int i = 1; i < 32; i += 2)
            if (w[i] != 0u) is64 = 0;
        g_is64 = is64;
    }
}

__global__ void k_zero_cnt() {
    int i = blockIdx.x * blockDim.x + threadIdx.x;
    if (i < NN) g_cnt[i] = 0;
}

// convert edge index to int32 + in-degree histogram (int atomics)
__global__ void k_convert_count(const void* __restrict__ ei) {
    int e = blockIdx.x * blockDim.x + threadIdx.x;
    if (e >= NE) return;
    int s, d;
    if (g_is64) {
        const long long* p = (const long long*)ei;
        s = (int)p[e];
        d = (int)p[(long long)NE + e];
    } else {
        const int* p = (const int*)ei;
        s = p[e];
        d = p[NE + e];
    }
    g_src32[e] = s;
    g_dst32[e] = d;
    atomicAdd(&g_cnt[d], 1);
}

// ---- exclusive prefix sum over g_cnt (3 kernels) ----
__global__ void k_scanA() {
    __shared__ int sh[SCAN_B];
    int i = blockIdx.x * SCAN_B + threadIdx.x;
    int v = (i < NN) ? g_cnt[i] : 0;
    sh[threadIdx.x] = v;
    __syncthreads();
    for (int off = 1; off < SCAN_B; off <<= 1) {
        int t = (threadIdx.x >= off) ? sh[threadIdx.x - off] : 0;
        __syncthreads();
        sh[threadIdx.x] += t;
        __syncthreads();
    }
    if (i < NN) g_rowstart[i] = sh[threadIdx.x] - v;   // within-block exclusive
    if (threadIdx.x == SCAN_B - 1) g_bsum[blockIdx.x] = sh[threadIdx.x];
}

__global__ void k_scanB() {
    __shared__ int sh[SCAN_B];
    int v = (threadIdx.x < NBLK) ? g_bsum[threadIdx.x] : 0;
    sh[threadIdx.x] = v;
    __syncthreads();
    for (int off = 1; off < SCAN_B; off <<= 1) {
        int t = (threadIdx.x >= off) ? sh[threadIdx.x - off] : 0;
        __syncthreads();
        sh[threadIdx.x] += t;
        __syncthreads();
    }
    if (threadIdx.x < NBLK) g_boff[threadIdx.x] = sh[threadIdx.x] - v;
}

__global__ void k_scanC() {
    int i = blockIdx.x * blockDim.x + threadIdx.x;
    if (i >= NN) return;
    int r = g_rowstart[i] + g_boff[i / SCAN_B];
    g_rowstart[i] = r;
    g_cursor[i]   = r;
}

// counting-sort fill: csr[pos++] = src, grouped by dst
__global__ void k_fill() {
    int e = blockIdx.x * blockDim.x + threadIdx.x;
    if (e >= NE) return;
    int d = g_dst32[e];
    int pos = atomicAdd(&g_cursor[d], 1);
    g_csr[pos] = g_src32[e];
}

// dinv + layer-1 GEMM (x[21] @ W1[21x16]), x tiled through smem, pre-scaled by dinv
__global__ void k_layer1_node(const float* __restrict__ x, const float* __restrict__ W1) {
    __shared__ float sW[21 * 16];
    __shared__ float sX[256 * 21];
    for (int t = threadIdx.x; t < 21 * 16; t += blockDim.x) sW[t] = W1[t];
    int base = blockIdx.x * 256;
    {
        long long gbase = (long long)base * 21;
        int lim = (NN - base) * 21;
        if (lim > 256 * 21) lim = 256 * 21;
        for (int t = threadIdx.x; t < lim; t += blockDim.x)
            sX[t] = x[gbase + t];
    }
    __syncthreads();
    int i = base + threadIdx.x;
    if (i >= NN) return;
    float di = rsqrtf((float)g_cnt[i] + 1.0f);   // +1 self-loop
    g_dinv[i] = di;
    const float* xi = &sX[threadIdx.x * 21];
    float acc[16];
    #pragma unroll
    for (int f = 0; f < 16; f++) acc[f] = 0.0f;
    #pragma unroll
    for (int k = 0; k < 21; k++) {
        float xk = xi[k];
        #pragma unroll
        for (int f = 0; f < 16; f++) acc[f] = fmaf(xk, sW[k * 16 + f], acc[f]);
    }
    float4* h1p = (float4*)&g_h1[i * 16];
    #pragma unroll
    for (int q = 0; q < 4; q++) {
        float4 v;
        v.x = acc[q * 4 + 0] * di;
        v.y = acc[q * 4 + 1] * di;
        v.z = acc[q * 4 + 2] * di;
        v.w = acc[q * 4 + 3] * di;
        h1p[q] = v;
    }
}

// gather layer 1: warp per dst node; 4 lanes/edge, 8 edges/iter; register accumulate
__global__ void k_gather1() {
    int i = blockIdx.x * 8 + (threadIdx.x >> 5);   // node id
    int lane = threadIdx.x & 31;
    int g = lane >> 2;   // edge slot 0..7
    int q = lane & 3;    // quad 0..3
    int start = g_rowstart[i];
    int n = g_cnt[i];
    float4 acc = make_float4(0.f, 0.f, 0.f, 0.f);
    for (int base = 0; base < n; base += 8) {
        int slot = base + lane;
        int v = (lane < 8 && slot < n) ? g_csr[start + slot] : -1;
        int s = __shfl_sync(0xffffffffu, v, g);
        if (s >= 0) {
            float4 h = *(const float4*)&g_h1[s * 16 + q * 4];
            acc.x += h.x; acc.y += h.y; acc.z += h.z; acc.w += h.w;
        }
    }
    #pragma unroll
    for (int off = 4; off < 32; off <<= 1) {
        acc.x += __shfl_xor_sync(0xffffffffu, acc.x, off);
        acc.y += __shfl_xor_sync(0xffffffffu, acc.y, off);
        acc.z += __shfl_xor_sync(0xffffffffu, acc.z, off);
        acc.w += __shfl_xor_sync(0xffffffffu, acc.w, off);
    }
    if (lane < 4) {   // lane == q
        float4 h = ((const float4*)&g_h1[i * 16])[lane];  // self-loop
        acc.x += h.x; acc.y += h.y; acc.z += h.z; acc.w += h.w;
        ((float4*)&g_agg1[i * 16])[lane] = acc;
    }
}

// relu(agg1*dinv + b1) @ W2[16x6], pre-scale, padded to 8
__global__ void k_layer2_node(const float* __restrict__ b1, const float* __restrict__ W2) {
    __shared__ float sW[16 * 6];
    __shared__ float sb[16];
    for (int t = threadIdx.x; t < 96; t += blockDim.x) sW[t] = W2[t];
    if (threadIdx.x < 16) sb[threadIdx.x] = b1[threadIdx.x];
    __syncthreads();
    int i = blockIdx.x * blockDim.x + threadIdx.x;
    if (i >= NN) return;
    float di = g_dinv[i];
    float v[16];
    const float4* a1p = (const float4*)&g_agg1[i * 16];
    #pragma unroll
    for (int qq = 0; qq < 4; qq++) {
        float4 a = a1p[qq];
        v[qq * 4 + 0] = fmaxf(a.x * di + sb[qq * 4 + 0], 0.0f);
        v[qq * 4 + 1] = fmaxf(a.y * di + sb[qq * 4 + 1], 0.0f);
        v[qq * 4 + 2] = fmaxf(a.z * di + sb[qq * 4 + 2], 0.0f);
        v[qq * 4 + 3] = fmaxf(a.w * di + sb[qq * 4 + 3], 0.0f);
    }
    float o[6];
    #pragma unroll
    for (int j = 0; j < 6; j++) {
        float s = 0.0f;
        #pragma unroll
        for (int f = 0; f < 16; f++) s = fmaf(v[f], sW[f * 6 + j], s);
        o[j] = s * di;
    }
    *(float4*)&g_h2[i * 8]     = make_float4(o[0], o[1], o[2], o[3]);
    *(float4*)&g_h2[i * 8 + 4] = make_float4(o[4], o[5], 0.0f, 0.0f);
}

// gather layer 2: warp per dst node; 2 lanes/edge, 16 edges/iter
__global__ void k_gather2() {
    int i = blockIdx.x * 8 + (threadIdx.x >> 5);
    int lane = threadIdx.x & 31;
    int g = lane >> 1;   // edge slot 0..15
    int q = lane & 1;    // half 0..1
    int start = g_rowstart[i];
    int n = g_cnt[i];
    float4 acc = make_float4(0.f, 0.f, 0.f, 0.f);
    for (int base = 0; base < n; base += 16) {
        int slot = base + lane;
        int v = (lane < 16 && slot < n) ? g_csr[start + slot] : -1;
        int s = __shfl_sync(0xffffffffu, v, g);
        if (s >= 0) {
            float4 h = *(const float4*)&g_h2[s * 8 + q * 4];
            acc.x += h.x; acc.y += h.y; acc.z += h.z; acc.w += h.w;
        }
    }
    #pragma unroll
    for (int off = 2; off < 32; off <<= 1) {
        acc.x += __shfl_xor_sync(0xffffffffu, acc.x, off);
        acc.y += __shfl_xor_sync(0xffffffffu, acc.y, off);
        acc.z += __shfl_xor_sync(0xffffffffu, acc.z, off);
        acc.w += __shfl_xor_sync(0xffffffffu, acc.w, off);
    }
    if (lane < 2) {   // lane == q
        float4 h = ((const float4*)&g_h2[i * 8])[lane];  // self-loop
        acc.x += h.x; acc.y += h.y; acc.z += h.z; acc.w += h.w;
        ((float4*)&g_agg2[i * 8])[lane] = acc;
    }
}

// final: agg2*dinv + b2, log_softmax over 6 classes
__global__ void k_out(const float* __restrict__ b2, float* __restrict__ out) {
    int i = blockIdx.x * blockDim.x + threadIdx.x;
    if (i >= NN) return;
    float di = g_dinv[i];
    float4 lo = *(const float4*)&g_agg2[i * 8];
    float2 hi = *(const float2*)&g_agg2[i * 8 + 4];
    float v[6];
    v[0] = lo.x * di + b2[0];
    v[1] = lo.y * di + b2[1];
    v[2] = lo.z * di + b2[2];
    v[3] = lo.w * di + b2[3];
    v[4] = hi.x * di + b2[4];
    v[5] = hi.y * di + b2[5];
    float m = v[0];
    #pragma unroll
    for (int j = 1; j < 6; j++) m = fmaxf(m, v[j]);
    float s = 0.0f;
    #pragma unroll
    for (int j = 0; j < 6; j++) s += expf(v[j] - m);
    float l = m + logf(s);
    #pragma unroll
    for (int j = 0; j < 6; j++) out[i * 6 + j] = v[j] - l;
}

extern "C" void kernel_launch(void* const* d_in, const int* in_sizes, int n_in,
                              void* d_out, int out_size) {
    const float* x  = (const float*)d_in[0];
    const void*  ei = d_in[1];
    const float* W1 = (const float*)d_in[2];
    const float* b1 = (const float*)d_in[3];
    const float* W2 = (const float*)d_in[4];
    const float* b2 = (const float*)d_in[5];
    float* out = (float*)d_out;

    const int T = 256;
    k_detect<<<1, 32>>>((const unsigned int*)ei);
    k_zero_cnt<<<(NN + T - 1) / T, T>>>();
    k_convert_count<<<(NE + T - 1) / T, T>>>(ei);
    k_scanA<<<NBLK, SCAN_B>>>();
    k_scanB<<<1, SCAN_B>>>();
    k_scanC<<<(NN + T - 1) / T, T>>>();
    k_layer1_node<<<(NN + 255) / 256, 256>>>(x, W1);
    k_fill<<<(NE + T - 1) / T, T>>>();
    k_gather1<<<NN / 8, 256>>>();
    k_layer2_node<<<(NN + T - 1) / T, T>>>(b1, W2);
    k_gather2<<<NN / 8, 256>>>();
    k_out<<<(NN + T - 1) / T, T>>>(b2, out);
}